// round 8
// baseline (speedup 1.0000x reference)
#include <cuda_runtime.h>

// TensorProductLayer, persistent double-buffered pipeline:
//  - grid-stride over 128-pair tiles; cp.async prefetch of tile t+stride
//    overlaps compute+store of tile t (wait_group 1 / depth-2 groups)
//  - per-thread scalar compute from smem (strides 1,3,9 coprime to 32)
//  - cooperative STG.128 stores
// Per pair: a=x0, b=y0, u=x1(3), v=y1(3), A=x2(9), B=y2(9)
//   out0      = a*b + u.v + <A,B>_F
//   out1[i]   = a*v[i] + b*u[i] + (u^T B)[i] + (A v)[i]
//   out2[i,j] = a*B[i,j] + b*A[i,j] + u[i]*v[j] + (A B)[i,j]

#define TPB 256      // threads per block
#define PT  128      // pairs per tile
#define BUF_F4 832   // float4 per buffer: sa 32 | sb 32 | su 96 | sv 96 | sA 288 | sB 288
// buffer float4 offsets: sa 0, sb 32, su 64, sv 160, sA 256, sB 544
// buffer float  offsets: sa 0, sb 128, su 256, sv 640, sA 1024, sB 2176

__device__ __forceinline__ void cp16(float4* smem_dst, const float4* gmem_src)
{
    unsigned saddr = (unsigned)__cvta_generic_to_shared(smem_dst);
    asm volatile("cp.async.cg.shared.global [%0], [%1], 16;"
                 :: "r"(saddr), "l"(gmem_src));
}

__device__ __forceinline__ void tp_pair(
    float a, float b,
    const float* __restrict__ u, const float* __restrict__ v,
    const float* __restrict__ A, const float* __restrict__ B,
    float* __restrict__ r0, float* __restrict__ r1, float* __restrict__ r2)
{
    float s0 = a * b;
#pragma unroll
    for (int i = 0; i < 3; ++i) s0 = fmaf(u[i], v[i], s0);
#pragma unroll
    for (int i = 0; i < 9; ++i) s0 = fmaf(A[i], B[i], s0);
    *r0 = s0;

#pragma unroll
    for (int i = 0; i < 3; ++i) {
        float t = a * v[i];
        t = fmaf(b, u[i], t);
#pragma unroll
        for (int d = 0; d < 3; ++d) t = fmaf(u[d], B[d * 3 + i], t);
#pragma unroll
        for (int e = 0; e < 3; ++e) t = fmaf(A[i * 3 + e], v[e], t);
        r1[i] = t;
    }

#pragma unroll
    for (int i = 0; i < 3; ++i) {
#pragma unroll
        for (int j = 0; j < 3; ++j) {
            float t = a * B[i * 3 + j];
            t = fmaf(b, A[i * 3 + j], t);
            t = fmaf(u[i], v[j], t);
#pragma unroll
            for (int e = 0; e < 3; ++e) t = fmaf(A[i * 3 + e], B[e * 3 + j], t);
            r2[i * 3 + j] = t;
        }
    }
}

// Stage one full 128-pair tile into buf via cp.async (832 f4 over 256 threads).
__device__ __forceinline__ void stage_tile(
    float4* buf, long long t, int tid,
    const float4* x0, const float4* y0, const float4* x1, const float4* y1,
    const float4* x2, const float4* y2)
{
    const long long g = t * (PT / 4);  // f4 index of tile start in rank-0 space
    // pass 0: i = tid in [0,256): sa | sb | su | sv
    {
        const float4* src;
        if (tid < 32)        src = x0 + g + tid;
        else if (tid < 64)   src = y0 + g + (tid - 32);
        else if (tid < 160)  src = x1 + g * 3 + (tid - 64);
        else                 src = y1 + g * 3 + (tid - 160);
        cp16(buf + tid, src);
    }
    // pass 1: i in [256,512): sA idx 0..255
    cp16(buf + 256 + tid, x2 + g * 9 + tid);
    // pass 2: i in [512,768): sA idx 256..287 then sB idx 0..223
    {
        int i = tid + 512;
        if (i < 544) cp16(buf + i, x2 + g * 9 + (i - 256));
        else         cp16(buf + i, y2 + g * 9 + (i - 544));
    }
    // pass 3: i in [768,832): sB idx 224..287
    if (tid < 64) cp16(buf + 768 + tid, y2 + g * 9 + 224 + tid);
}

__global__ void __launch_bounds__(TPB)
tp_kernel_pipe(const float* __restrict__ x0f, const float* __restrict__ y0f,
               const float* __restrict__ x1f, const float* __restrict__ y1f,
               const float* __restrict__ x2f, const float* __restrict__ y2f,
               float* __restrict__ o0f, float* __restrict__ o1f, float* __restrict__ o2f,
               int total)
{
    __shared__ float4 sbuf[2 * BUF_F4];   // 26,624 B

    const int tid = threadIdx.x;
    const long long stride = gridDim.x;
    const long long nt = ((long long)total + PT - 1) / PT;
    long long t0 = blockIdx.x;
    if (t0 >= nt) return;

    const float4* x0 = reinterpret_cast<const float4*>(x0f);
    const float4* y0 = reinterpret_cast<const float4*>(y0f);
    const float4* x1 = reinterpret_cast<const float4*>(x1f);
    const float4* y1 = reinterpret_cast<const float4*>(y1f);
    const float4* x2 = reinterpret_cast<const float4*>(x2f);
    const float4* y2 = reinterpret_cast<const float4*>(y2f);
    float4* o0 = reinterpret_cast<float4*>(o0f);
    float4* o1 = reinterpret_cast<float4*>(o1f);
    float4* o2 = reinterpret_cast<float4*>(o2f);

    // prologue: prefetch first tile (if full) into buf 0
    if (t0 * PT + PT <= total)
        stage_tile(sbuf, t0, tid, x0, y0, x1, y1, x2, y2);
    asm volatile("cp.async.commit_group;");

    int k = 0;
    for (long long t = t0; t < nt; t += stride, ++k) {
        // prefetch next tile into the other buffer
        long long tn = t + stride;
        if (tn < nt && tn * PT + PT <= total)
            stage_tile(sbuf + ((k + 1) & 1) * BUF_F4, tn, tid, x0, y0, x1, y1, x2, y2);
        asm volatile("cp.async.commit_group;");
        asm volatile("cp.async.wait_group 1;");   // current tile's group complete
        __syncthreads();

        float4* buf = sbuf + (k & 1) * BUF_F4;

        if (t * PT + PT <= total) {
            // ---- compute: threads 0..127, one pair each, results in place ----
            if (tid < PT) {
                float* f = reinterpret_cast<float*>(buf);
                float a = f[tid], b = f[128 + tid];
                float u[3], v[3], A[9], B[9];
#pragma unroll
                for (int i = 0; i < 3; ++i) { u[i] = f[256 + tid * 3 + i]; v[i] = f[640 + tid * 3 + i]; }
#pragma unroll
                for (int i = 0; i < 9; ++i) { A[i] = f[1024 + tid * 9 + i]; B[i] = f[2176 + tid * 9 + i]; }

                float r0, r1[3], r2[9];
                tp_pair(a, b, u, v, A, B, &r0, r1, r2);

                f[tid] = r0;
#pragma unroll
                for (int i = 0; i < 3; ++i) f[256 + tid * 3 + i] = r1[i];
#pragma unroll
                for (int i = 0; i < 9; ++i) f[1024 + tid * 9 + i] = r2[i];
            }
            __syncthreads();

            // ---- store: 416 f4 over 256 threads ----
            {
                const long long g = t * (PT / 4);
                if (tid < 32)
                    __stcs(o0 + g + tid, buf[tid]);
                else if (tid < 128)
                    __stcs(o1 + g * 3 + (tid - 32), buf[64 + (tid - 32)]);
                else
                    __stcs(o2 + g * 9 + (tid - 128), buf[256 + (tid - 128)]);
                if (tid < 160)
                    __stcs(o2 + g * 9 + 128 + tid, buf[384 + tid]);
            }
        } else {
            // ---- partial tail tile: scalar direct-gmem ----
            long long p = t * PT + tid;
            if (tid < PT && p < total) {
                float a = x0f[p], b = y0f[p];
                float u[3], v[3], A[9], B[9];
#pragma unroll
                for (int i = 0; i < 3; ++i) { u[i] = x1f[p * 3 + i]; v[i] = y1f[p * 3 + i]; }
#pragma unroll
                for (int i = 0; i < 9; ++i) { A[i] = x2f[p * 9 + i]; B[i] = y2f[p * 9 + i]; }
                float r0, r1[3], r2[9];
                tp_pair(a, b, u, v, A, B, &r0, r1, r2);
                o0f[p] = r0;
#pragma unroll
                for (int i = 0; i < 3; ++i) o1f[p * 3 + i] = r1[i];
#pragma unroll
                for (int i = 0; i < 9; ++i) o2f[p * 9 + i] = r2[i];
            }
        }
        __syncthreads();   // buffer free before next iteration's prefetch overwrites it
    }
}

extern "C" void kernel_launch(void* const* d_in, const int* in_sizes, int n_in,
                              void* d_out, int out_size)
{
    // Resolve inputs by element count: s = base (rank-0), 3s (rank-1), 9s (rank-2).
    // First occurrence of a size = x tensor, second = y tensor (robust to both
    // metadata orderings).
    int s = in_sizes[0];
    for (int i = 1; i < n_in; ++i) if (in_sizes[i] < s) s = in_sizes[i];

    const float* X[3] = {nullptr, nullptr, nullptr};
    const float* Y[3] = {nullptr, nullptr, nullptr};
    for (int i = 0; i < n_in; ++i) {
        int r;
        if (in_sizes[i] == s)          r = 0;
        else if (in_sizes[i] == 3 * s) r = 1;
        else                           r = 2;
        if (X[r] == nullptr) X[r] = (const float*)d_in[i];
        else                 Y[r] = (const float*)d_in[i];
    }

    float* o0 = (float*)d_out;       // s elements
    float* o1 = o0 + (size_t)s;      // 3s elements
    float* o2 = o0 + (size_t)4 * s;  // 9s elements

    long long nt = ((long long)s + PT - 1) / PT;
    int blocks = (int)((nt < 1184) ? nt : 1184);   // 148 SMs x 8 CTAs
    tp_kernel_pipe<<<blocks, TPB>>>(X[0], Y[0], X[1], Y[1], X[2], Y[2],
                                    o0, o1, o2, s);
}

// round 9
// speedup vs baseline: 1.1286x; 1.1286x over previous
#include <cuda_runtime.h>

// TensorProductLayer, smem-staged, split-tile cp.async pipeline (straight-line):
//  - block = 256 pairs as two 128-pair half-tiles, each its own cp.async group
//  - compute+store of half 0 overlaps arrival of half 1 (wait_group 1 -> 0)
//  - per-thread scalar compute from smem (strides 1,3,9 coprime to 32)
//  - cooperative STG.128 stores; all indexing 32-bit
// Per pair: a=x0, b=y0, u=x1(3), v=y1(3), A=x2(9), B=y2(9)
//   out0      = a*b + u.v + <A,B>_F
//   out1[i]   = a*v[i] + b*u[i] + (u^T B)[i] + (A v)[i]
//   out2[i,j] = a*B[i,j] + b*A[i,j] + u[i]*v[j] + (A B)[i,j]

#define TPB 256      // threads per block
#define PT  128      // pairs per half-tile
#define BUF_F4 832   // f4 per half-tile buffer
// per-buffer f4 offsets:    sa 0, sb 32, su 64, sv 160, sA 256, sB 544
// per-buffer float offsets: sa 0, sb 128, su 256, sv 640, sA 1024, sB 2176

__device__ __forceinline__ void cp16(float4* smem_dst, const float4* gmem_src)
{
    unsigned saddr = (unsigned)__cvta_generic_to_shared(smem_dst);
    asm volatile("cp.async.cg.shared.global [%0], [%1], 16;"
                 :: "r"(saddr), "l"(gmem_src));
}

__device__ __forceinline__ void tp_pair(
    float a, float b,
    const float* __restrict__ u, const float* __restrict__ v,
    const float* __restrict__ A, const float* __restrict__ B,
    float* __restrict__ r0, float* __restrict__ r1, float* __restrict__ r2)
{
    float s0 = a * b;
#pragma unroll
    for (int i = 0; i < 3; ++i) s0 = fmaf(u[i], v[i], s0);
#pragma unroll
    for (int i = 0; i < 9; ++i) s0 = fmaf(A[i], B[i], s0);
    *r0 = s0;

#pragma unroll
    for (int i = 0; i < 3; ++i) {
        float t = a * v[i];
        t = fmaf(b, u[i], t);
#pragma unroll
        for (int d = 0; d < 3; ++d) t = fmaf(u[d], B[d * 3 + i], t);
#pragma unroll
        for (int e = 0; e < 3; ++e) t = fmaf(A[i * 3 + e], v[e], t);
        r1[i] = t;
    }

#pragma unroll
    for (int i = 0; i < 3; ++i) {
#pragma unroll
        for (int j = 0; j < 3; ++j) {
            float t = a * B[i * 3 + j];
            t = fmaf(b, A[i * 3 + j], t);
            t = fmaf(u[i], v[j], t);
#pragma unroll
            for (int e = 0; e < 3; ++e) t = fmaf(A[i * 3 + e], B[e * 3 + j], t);
            r2[i * 3 + j] = t;
        }
    }
}

// Stage one 128-pair half-tile (832 f4) into buf over 256 threads.
// g = f4 index of half-tile start in rank-0 space (all fits in 32-bit).
__device__ __forceinline__ void stage_half(
    float4* buf, int g, int tid,
    const float4* __restrict__ x0, const float4* __restrict__ y0,
    const float4* __restrict__ x1, const float4* __restrict__ y1,
    const float4* __restrict__ x2, const float4* __restrict__ y2)
{
    const int g3 = g * 3, g9 = g * 9;
    // pass 0: sa(32) | sb(32) | su(96) | sv(96)
    {
        const float4* src;
        if (tid < 32)        src = x0 + (g + tid);
        else if (tid < 64)   src = y0 + (g + tid - 32);
        else if (tid < 160)  src = x1 + (g3 + tid - 64);
        else                 src = y1 + (g3 + tid - 160);
        cp16(buf + tid, src);
    }
    // pass 1: sA f4 0..255
    cp16(buf + 256 + tid, x2 + (g9 + tid));
    // pass 2: sA f4 256..287 (32) then sB f4 0..223 (224)
    if (tid < 32) cp16(buf + 512 + tid, x2 + (g9 + 256 + tid));
    else          cp16(buf + 512 + tid, y2 + (g9 + tid - 32));
    // pass 3: sB f4 224..287 (64)
    if (tid < 64) cp16(buf + 768 + tid, y2 + (g9 + 224 + tid));
}

// Compute 128 pairs in place (threads 0..127 only).
__device__ __forceinline__ void compute_half(float4* buf, int tid)
{
    if (tid < PT) {
        float* f = reinterpret_cast<float*>(buf);
        float a = f[tid], b = f[128 + tid];
        float u[3], v[3], A[9], B[9];
#pragma unroll
        for (int i = 0; i < 3; ++i) { u[i] = f[256 + tid * 3 + i]; v[i] = f[640 + tid * 3 + i]; }
#pragma unroll
        for (int i = 0; i < 9; ++i) { A[i] = f[1024 + tid * 9 + i]; B[i] = f[2176 + tid * 9 + i]; }

        float r0, r1[3], r2[9];
        tp_pair(a, b, u, v, A, B, &r0, r1, r2);

        f[tid] = r0;
#pragma unroll
        for (int i = 0; i < 3; ++i) f[256 + tid * 3 + i] = r1[i];
#pragma unroll
        for (int i = 0; i < 9; ++i) f[1024 + tid * 9 + i] = r2[i];
    }
}

// Store results of one half-tile (416 f4) over 256 threads.
__device__ __forceinline__ void store_half(
    const float4* buf, int g, int tid,
    float4* __restrict__ o0, float4* __restrict__ o1, float4* __restrict__ o2)
{
    const int g3 = g * 3, g9 = g * 9;
    if (tid < 32)
        __stcs(o0 + (g + tid), buf[tid]);
    else if (tid < 128)
        __stcs(o1 + (g3 + tid - 32), buf[64 + (tid - 32)]);
    else
        __stcs(o2 + (g9 + tid - 128), buf[256 + (tid - 128)]);
    if (tid < 160)
        __stcs(o2 + (g9 + 128 + tid), buf[384 + tid]);
}

__global__ void __launch_bounds__(TPB)
tp_kernel_split(const float* __restrict__ x0f, const float* __restrict__ y0f,
                const float* __restrict__ x1f, const float* __restrict__ y1f,
                const float* __restrict__ x2f, const float* __restrict__ y2f,
                float* __restrict__ o0f, float* __restrict__ o1f, float* __restrict__ o2f,
                int total)
{
    __shared__ float4 sbuf[2 * BUF_F4];   // 26,624 B -> 8 CTAs/SM

    const int tid = threadIdx.x;
    const int P0 = blockIdx.x * (2 * PT);

    const float4* x0 = reinterpret_cast<const float4*>(x0f);
    const float4* y0 = reinterpret_cast<const float4*>(y0f);
    const float4* x1 = reinterpret_cast<const float4*>(x1f);
    const float4* y1 = reinterpret_cast<const float4*>(y1f);
    const float4* x2 = reinterpret_cast<const float4*>(x2f);
    const float4* y2 = reinterpret_cast<const float4*>(y2f);
    float4* o0 = reinterpret_cast<float4*>(o0f);
    float4* o1 = reinterpret_cast<float4*>(o1f);
    float4* o2 = reinterpret_cast<float4*>(o2f);

    if (P0 + 2 * PT <= total) {
        // ================= fast path: two full half-tiles =================
        const int g0 = P0 >> 2;          // f4 index of half 0
        const int g1 = g0 + (PT >> 2);   // f4 index of half 1

        stage_half(sbuf, g0, tid, x0, y0, x1, y1, x2, y2);
        asm volatile("cp.async.commit_group;");
        stage_half(sbuf + BUF_F4, g1, tid, x0, y0, x1, y1, x2, y2);
        asm volatile("cp.async.commit_group;");

        // half 0: compute+store while half 1 still in flight
        asm volatile("cp.async.wait_group 1;");
        __syncthreads();
        compute_half(sbuf, tid);
        __syncthreads();
        store_half(sbuf, g0, tid, o0, o1, o2);

        // half 1
        asm volatile("cp.async.wait_group 0;");
        __syncthreads();
        compute_half(sbuf + BUF_F4, tid);
        __syncthreads();
        store_half(sbuf + BUF_F4, g1, tid, o0, o1, o2);
    } else {
        // ================= tail path: scalar with guards =================
        for (int h = 0; h < 2; ++h) {
            int p = P0 + h * PT + tid;
            if (tid < PT && p < total) {
                float a = x0f[p], b = y0f[p];
                float u[3], v[3], A[9], B[9];
#pragma unroll
                for (int i = 0; i < 3; ++i) { u[i] = x1f[p * 3 + i]; v[i] = y1f[p * 3 + i]; }
#pragma unroll
                for (int i = 0; i < 9; ++i) { A[i] = x2f[p * 9 + i]; B[i] = y2f[p * 9 + i]; }
                float r0, r1[3], r2[9];
                tp_pair(a, b, u, v, A, B, &r0, r1, r2);
                o0f[p] = r0;
#pragma unroll
                for (int i = 0; i < 3; ++i) o1f[p * 3 + i] = r1[i];
#pragma unroll
                for (int i = 0; i < 9; ++i) o2f[p * 9 + i] = r2[i];
            }
        }
    }
}

extern "C" void kernel_launch(void* const* d_in, const int* in_sizes, int n_in,
                              void* d_out, int out_size)
{
    // Resolve inputs by element count: s = base (rank-0), 3s (rank-1), 9s (rank-2).
    // First occurrence of a size = x tensor, second = y tensor (robust to both
    // metadata orderings).
    int s = in_sizes[0];
    for (int i = 1; i < n_in; ++i) if (in_sizes[i] < s) s = in_sizes[i];

    const float* X[3] = {nullptr, nullptr, nullptr};
    const float* Y[3] = {nullptr, nullptr, nullptr};
    for (int i = 0; i < n_in; ++i) {
        int r;
        if (in_sizes[i] == s)          r = 0;
        else if (in_sizes[i] == 3 * s) r = 1;
        else                           r = 2;
        if (X[r] == nullptr) X[r] = (const float*)d_in[i];
        else                 Y[r] = (const float*)d_in[i];
    }

    float* o0 = (float*)d_out;       // s elements
    float* o1 = o0 + (size_t)s;      // 3s elements
    float* o2 = o0 + (size_t)4 * s;  // 9s elements

    int blocks = (s + 2 * PT - 1) / (2 * PT);
    tp_kernel_split<<<blocks, TPB>>>(X[0], Y[0], X[1], Y[1], X[2], Y[2],
                                     o0, o1, o2, s);
}